// round 16
// baseline (speedup 1.0000x reference)
#include <cuda_runtime.h>
#include <cstdint>

#define EMB     128
#define N_IN    256
#define HID     64
#define HROW    128          // Htop[64] | Hbot[64] per node
#define N_NODES 100000
#define PC_TPB  256
#define PC_NPB  512          // nodes per block (2 per thread)
#define EG_TPB  256
#define EG_GRID 592

// 51.2 MB scratch: per-node hidden pre-activations (static __device__ = allowed)
__device__ float g_H[(size_t)N_NODES * HROW];

// ---- packed f32x2 helpers (Blackwell dual-FMA pipe) ----
__device__ __forceinline__ void fma2(unsigned long long& d, unsigned long long a,
                                     unsigned long long b, unsigned long long c)
{
    asm("fma.rn.f32x2 %0, %1, %2, %3;" : "=l"(d) : "l"(a), "l"(b), "l"(c));
}
__device__ __forceinline__ unsigned long long bcast2(float x)
{
    unsigned long long r; unsigned int xi = __float_as_uint(x);
    asm("mov.b64 %0, {%1, %2};" : "=l"(r) : "r"(xi), "r"(xi));
    return r;
}
__device__ __forceinline__ unsigned long long pack2(float lo, float hi)
{
    unsigned long long r;
    asm("mov.b64 %0, {%1, %2};" : "=l"(r) : "r"(__float_as_uint(lo)), "r"(__float_as_uint(hi)));
    return r;
}
__device__ __forceinline__ void unpack2(unsigned long long p, float& lo, float& hi)
{
    unsigned int l, h;
    asm("mov.b64 {%0, %1}, %2;" : "=r"(l), "=r"(h) : "l"(p));
    lo = __uint_as_float(l); hi = __uint_as_float(h);
}

// ---- Phase 1: per-node hidden pre-activations, 2 nodes per thread ----
// Htop[n][j] = emb[n]·W1[0:128][j] + b1[j] ; Hbot[n][j] = emb[n]·W1[128:256][j]
// Each LDS.128 of W feeds 4 fma2 (2 nodes) -> issue ratio 1:4.
__global__ __launch_bounds__(PC_TPB)
void precompute_kernel(const float* __restrict__ emb,
                       const float* __restrict__ W1,
                       const float* __restrict__ b1)
{
    extern __shared__ float sm[];
    float* W1s = sm;               // [256][64]
    float* b1s = sm + N_IN * HID;  // [64]
    {
        const float4* src = reinterpret_cast<const float4*>(W1);
        float4* dst = reinterpret_cast<float4*>(W1s);
        #pragma unroll 4
        for (int i = threadIdx.x; i < (N_IN * HID) / 4; i += PC_TPB)
            dst[i] = src[i];
        if (threadIdx.x < HID) b1s[threadIdx.x] = b1[threadIdx.x];
    }
    __syncthreads();

    int n0 = blockIdx.x * PC_NPB + threadIdx.x;
    int n1 = n0 + PC_TPB;
    bool v0 = n0 < N_NODES;
    bool v1 = n1 < N_NODES;
    int c0 = v0 ? n0 : N_NODES - 1;
    int c1 = v1 ? n1 : N_NODES - 1;
    const float4* row0 = reinterpret_cast<const float4*>(emb + (size_t)c0 * EMB);
    const float4* row1 = reinterpret_cast<const float4*>(emb + (size_t)c1 * EMB);

    #pragma unroll 1
    for (int half = 0; half < 2; half++) {
        unsigned long long a0[HID / 2], a1[HID / 2];
        #pragma unroll
        for (int j = 0; j < HID / 2; j++) {
            unsigned long long init = (half == 0) ? pack2(b1s[2 * j], b1s[2 * j + 1]) : 0ULL;
            a0[j] = init;
            a1[j] = init;
        }

        #pragma unroll 1
        for (int c = 0; c < EMB / 4; c++) {
            float4 x0 = row0[c];
            float4 x1 = row1[c];
            float xs0[4] = {x0.x, x0.y, x0.z, x0.w};
            float xs1[4] = {x1.x, x1.y, x1.z, x1.w};
            #pragma unroll
            for (int kk = 0; kk < 4; kk++) {
                const ulonglong2* wv = reinterpret_cast<const ulonglong2*>(
                    W1s + (half * EMB + c * 4 + kk) * HID);
                unsigned long long xb0 = bcast2(xs0[kk]);
                unsigned long long xb1 = bcast2(xs1[kk]);
                #pragma unroll
                for (int j = 0; j < HID / 4; j++) {   // 16 LDS.128 -> 64 fma2
                    ulonglong2 w = wv[j];
                    fma2(a0[2 * j + 0], xb0, w.x, a0[2 * j + 0]);
                    fma2(a0[2 * j + 1], xb0, w.y, a0[2 * j + 1]);
                    fma2(a1[2 * j + 0], xb1, w.x, a1[2 * j + 0]);
                    fma2(a1[2 * j + 1], xb1, w.y, a1[2 * j + 1]);
                }
            }
        }
        if (v0) {
            float4* dst = reinterpret_cast<float4*>(g_H + (size_t)n0 * HROW + half * HID);
            #pragma unroll
            for (int j = 0; j < HID / 4; j++) {
                float4 o;
                unpack2(a0[2 * j + 0], o.x, o.y);
                unpack2(a0[2 * j + 1], o.z, o.w);
                dst[j] = o;
            }
        }
        if (v1) {
            float4* dst = reinterpret_cast<float4*>(g_H + (size_t)n1 * HROW + half * HID);
            #pragma unroll
            for (int j = 0; j < HID / 4; j++) {
                float4 o;
                unpack2(a1[2 * j + 0], o.x, o.y);
                unpack2(a1[2 * j + 1], o.z, o.w);
                dst[j] = o;
            }
        }
    }
}

// ---- Phase 2: per-edge score. Warp-cooperative: lane l owns hid {2l,2l+1}. ----
__global__ __launch_bounds__(EG_TPB)
void edge_kernel(const int* __restrict__ ei,
                 const float* __restrict__ W2,
                 const float* __restrict__ b2,
                 float* __restrict__ out,
                 int E)
{
    int lane = threadIdx.x & 31;
    int gwarp = (blockIdx.x * EG_TPB + threadIdx.x) >> 5;
    int nwarps = (EG_GRID * EG_TPB) >> 5;
    // dtype detect inline (uniform, cached): int64 ids < 2^31 -> odd words all 0
    bool is64 = (ei[1] == 0 && ei[3] == 0 && ei[5] == 0 && ei[7] == 0);

    float w2x = W2[2 * lane];
    float w2y = W2[2 * lane + 1];
    float b2v = b2[0];

    #pragma unroll 1
    for (int base = gwarp * 8; base < E; base += nwarps * 8) {
        // lanes 0-7: src ids of edges base..base+7; lanes 8-15: tgt ids
        int id = 0;
        if (lane < 16) {
            int e = min(base + (lane & 7), E - 1);
            int half = lane >> 3;
            if (is64) {
                id = (int)reinterpret_cast<const long long*>(ei)[(size_t)half * E + e];
            } else {
                id = ei[(size_t)half * E + e];
            }
            id = min(max(id, 0), N_NODES - 1);
        }

        // 16 independent L2-resident loads in flight
        float2 hs[8], ht[8];
        #pragma unroll
        for (int u = 0; u < 8; u++) {
            int s = __shfl_sync(0xffffffffu, id, u);
            int t = __shfl_sync(0xffffffffu, id, u + 8);
            hs[u] = *reinterpret_cast<const float2*>(g_H + (size_t)s * HROW + 2 * lane);
            ht[u] = *reinterpret_cast<const float2*>(g_H + (size_t)t * HROW + HID + 2 * lane);
        }

        float p[8];
        #pragma unroll
        for (int u = 0; u < 8; u++) {
            float v0 = fmaxf(hs[u].x + ht[u].x, 0.f);
            float v1 = fmaxf(hs[u].y + ht[u].y, 0.f);
            p[u] = fmaf(v0, w2x, v1 * w2y);
        }

        // Halving multi-value reduction: 16 shfl + 16 add + 7 sel (vs 40+40).
        // Invariant: after xor-d round, values identical across lanes differing
        // in bit d -> select by that bit keeps a valid reduction target.
        #pragma unroll
        for (int u = 0; u < 8; u++)
            p[u] += __shfl_xor_sync(0xffffffffu, p[u], 16);
        float q[4];
        #pragma unroll
        for (int v = 0; v < 4; v++)
            q[v] = (lane & 16) ? p[v + 4] : p[v];
        #pragma unroll
        for (int v = 0; v < 4; v++)
            q[v] += __shfl_xor_sync(0xffffffffu, q[v], 8);
        float r0 = (lane & 8) ? q[2] : q[0];
        float r1 = (lane & 8) ? q[3] : q[1];
        r0 += __shfl_xor_sync(0xffffffffu, r0, 4);
        r1 += __shfl_xor_sync(0xffffffffu, r1, 4);
        float s = (lane & 4) ? r1 : r0;
        s += __shfl_xor_sync(0xffffffffu, s, 2);
        s += __shfl_xor_sync(0xffffffffu, s, 1);
        // lane 4u now holds the full sum for edge base+u  (u = b4*4 + b3*2 + b2)
        if ((lane & 3) == 0) {
            int e = base + (lane >> 2);
            if (e < E) out[e] = s + b2v;
        }
    }
}

extern "C" void kernel_launch(void* const* d_in, const int* in_sizes, int n_in,
                              void* d_out, int out_size)
{
    const float* emb = (const float*)d_in[0];   // [100000,128] f32
    const int*   ei  = (const int*)d_in[1];     // [2,E] int32 or int64
    const float* W1  = (const float*)d_in[2];   // [256,64]
    const float* b1  = (const float*)d_in[3];   // [64]
    const float* W2  = (const float*)d_in[4];   // [64,1]
    const float* b2  = (const float*)d_in[5];   // [1]
    float* out = (float*)d_out;
    int E = out_size;

    int pc_smem = (N_IN * HID + HID) * sizeof(float);   // ~65.8 KB
    cudaFuncSetAttribute(precompute_kernel,
                         cudaFuncAttributeMaxDynamicSharedMemorySize, pc_smem);

    int pc_grid = (N_NODES + PC_NPB - 1) / PC_NPB;      // 196
    precompute_kernel<<<pc_grid, PC_TPB, pc_smem>>>(emb, W1, b1);
    edge_kernel<<<EG_GRID, EG_TPB>>>(ei, W2, b2, out, E);
}